// round 2
// baseline (speedup 1.0000x reference)
#include <cuda_runtime.h>
#include <cuda_bf16.h>

#define NTOT 524288
#define DIM  128
#define S    128
#define G    (NTOT / S)
#define MARGIN   2.0f
#define K_MARGIN 0.02f
#define EPS      1e-6f

// Per-group scratch (static device allocation — allowed).
__device__ float g_loss[G];
__device__ float g_sumb[G];
__device__ float g_sump[G];
__device__ int   g_cntb[G];

// ---------------------------------------------------------------------------
// Kernel 1: d[i] = 1 - dot(z_r[i], z_v[i]).  One warp per row, float4 loads.
// 512 MB read -> HBM-bound.
// ---------------------------------------------------------------------------
__global__ void __launch_bounds__(256) dot_kernel(
    const float4* __restrict__ zr, const float4* __restrict__ zv,
    float* __restrict__ dout)
{
    int gw   = (blockIdx.x * blockDim.x + threadIdx.x) >> 5;   // row id
    int lane = threadIdx.x & 31;
    size_t off = (size_t)gw * 32 + lane;                       // 32 float4 per row
    float4 a = zr[off];
    float4 b = zv[off];
    float s = a.x * b.x + a.y * b.y + a.z * b.z + a.w * b.w;
    #pragma unroll
    for (int o = 16; o; o >>= 1) s += __shfl_xor_sync(0xffffffffu, s, o);
    if (lane == 0) dout[gw] = 1.0f - s;
}

// ---------------------------------------------------------------------------
// Block-wide sum over 128 threads (4 warps). All threads get result.
// ---------------------------------------------------------------------------
__device__ __forceinline__ float blockSum128(float v, float* red)
{
    #pragma unroll
    for (int o = 16; o; o >>= 1) v += __shfl_xor_sync(0xffffffffu, v, o);
    int w = threadIdx.x >> 5;
    if ((threadIdx.x & 31) == 0) red[w] = v;
    __syncthreads();
    float r = red[0] + red[1] + red[2] + red[3];
    __syncthreads();
    return r;
}

// ---------------------------------------------------------------------------
// Kernel 2: one CTA (128 threads) per group.
//   - label-partition sums of d (for l_cdd)
//   - corr_loss  (two-pass mean/var, ddof=1, eps, zero-std guard)
//   - STABLE counting sort by var_len (matches jnp.argsort stable)
//   - neigh_viol on sorted d
//   - rank_loss on sorted arrays, upper triangle with strict v inequality
// ---------------------------------------------------------------------------
__global__ void __launch_bounds__(S) group_kernel(
    const float* __restrict__ dvec, const int* __restrict__ var_lens,
    const int* __restrict__ labels)
{
    __shared__ float sd[S];     // d (original order)
    __shared__ int   sv[S];     // v (original order)
    __shared__ float sds[S];    // d sorted by v (stable)
    __shared__ int   svs[S];    // v sorted
    __shared__ int   cnt[100];  // counting-sort bins / start offsets
    __shared__ float red[4];

    const int g   = blockIdx.x;
    const int tid = threadIdx.x;
    const int idx = g * S + tid;

    int   v  = var_lens[idx];
    v = min(max(v, 0), 99);
    float di = dvec[idx];
    int   lb = labels[idx];

    sd[tid] = di;
    sv[tid] = v;
    if (tid < 100) cnt[tid] = 0;
    __syncthreads();

    // ---- label sums (contrastive term) ----
    float sb = blockSum128(lb == 0 ? di : 0.0f, red);
    float sp = blockSum128(lb == 1 ? di : 0.0f, red);
    float cb = blockSum128(lb == 0 ? 1.0f : 0.0f, red);

    // ---- correlation loss ----
    float vf    = (float)v;
    float meanv = blockSum128(vf, red) * (1.0f / S);
    float meand = blockSum128(di, red) * (1.0f / S);
    float dv0 = vf - meanv;
    float dd0 = di - meand;
    float ssv = blockSum128(dv0 * dv0, red);
    float ssd = blockSum128(dd0 * dd0, red);
    float vs = sqrtf(ssv * (1.0f / (S - 1)));
    float ds = sqrtf(ssd * (1.0f / (S - 1)));
    float vz = dv0 / (vs + EPS);
    float dz = dd0 / (ds + EPS);
    float corr = blockSum128((vz - dz) * (vz - dz), red) * (1.0f / S);
    if (!(vs > 0.0f && ds > 0.0f)) corr = 0.0f;

    // ---- stable counting sort by v ----
    atomicAdd(&cnt[v], 1);
    __syncthreads();
    if (tid == 0) {
        int run = 0;
        #pragma unroll 4
        for (int b = 0; b < 100; b++) { int c = cnt[b]; cnt[b] = run; run += c; }
    }
    __syncthreads();
    int rank = 0;
    #pragma unroll 8
    for (int j = 0; j < S; j++) rank += (j < tid) & (sv[j] == v);
    int pos = cnt[v] + rank;
    sds[pos] = di;
    svs[pos] = v;
    __syncthreads();

    // ---- neighbor violation (mean over S-1 adjacent sorted pairs) ----
    float nv = (tid < S - 1) ? fmaxf(sds[tid] - sds[tid + 1] + K_MARGIN, 0.0f) : 0.0f;
    float neigh = blockSum128(nv, red) * (1.0f / (S - 1));

    // ---- rank loss: pairs with strictly greater v; sorted => only j>i ----
    int   vi  = svs[tid];
    float ddi = sds[tid];
    float viol = 0.0f;
    int   c    = 0;
    for (int j = tid + 1; j < S; j++) {
        int vj = svs[j];
        if (vj > vi) {
            c++;
            viol += fmaxf(K_MARGIN - (sds[j] - ddi), 0.0f);
        }
    }
    float ctot = blockSum128((float)c, red);
    float vtot = blockSum128(viol, red);
    float rankl = (ctot > 0.0f) ? vtot / ctot : 0.0f;

    if (tid == 0) {
        g_loss[g] = corr + neigh + rankl;
        g_sumb[g] = sb;
        g_sump[g] = sp;
        g_cntb[g] = (int)cb;
    }
}

// ---------------------------------------------------------------------------
// Kernel 3: deterministic double-precision final reduction -> out[0], out[1].
// ---------------------------------------------------------------------------
__global__ void __launch_bounds__(256) finalize_kernel(float* __restrict__ out)
{
    __shared__ double shL[256], shB[256], shP[256];
    __shared__ long long shC[256];
    int tid = threadIdx.x;

    double aL = 0.0, aB = 0.0, aP = 0.0;
    long long cB = 0;
    for (int g = tid; g < G; g += 256) {
        aL += (double)g_loss[g];
        aB += (double)g_sumb[g];
        aP += (double)g_sump[g];
        cB += (long long)g_cntb[g];
    }
    shL[tid] = aL; shB[tid] = aB; shP[tid] = aP; shC[tid] = cB;
    __syncthreads();
    for (int s = 128; s > 0; s >>= 1) {
        if (tid < s) {
            shL[tid] += shL[tid + s];
            shB[tid] += shB[tid + s];
            shP[tid] += shP[tid + s];
            shC[tid] += shC[tid + s];
        }
        __syncthreads();
    }
    if (tid == 0) {
        long long nb = shC[0];
        long long np = (long long)NTOT - nb;
        double mb = shB[0] / (double)(nb > 1 ? nb : 1);
        double mp = shP[0] / (double)(np > 1 ? np : 1);
        double lcdd = (nb > 0 && np > 0) ? (MARGIN + mb - mp) : 0.0;
        if (lcdd < 0.0) lcdd = 0.0;
        out[0] = (float)lcdd;
        out[1] = (float)(shL[0] / (double)G);
    }
}

// ---------------------------------------------------------------------------
extern "C" void kernel_launch(void* const* d_in, const int* in_sizes, int n_in,
                              void* d_out, int out_size)
{
    const float* zr       = (const float*)d_in[0];
    const float* zv       = (const float*)d_in[1];
    const int*   labels   = (const int*)d_in[2];
    // d_in[3] = groups (== i / S by construction, unused)
    const int*   var_lens = (const int*)d_in[4];
    float* out  = (float*)d_out;
    float* dvec = out + 2;   // d occupies out[2 .. 2+N)

    dot_kernel<<<NTOT / 8, 256>>>((const float4*)zr, (const float4*)zv, dvec);
    group_kernel<<<G, S>>>(dvec, var_lens, labels);
    finalize_kernel<<<1, 256>>>(out);
}

// round 3
// speedup vs baseline: 1.0151x; 1.0151x over previous
#include <cuda_runtime.h>
#include <cuda_bf16.h>

#define NTOT 524288
#define DIM  128
#define S    128
#define G    (NTOT / S)
#define MARGIN   2.0f
#define K_MARGIN 0.02f
#define EPS      1e-6f

// Per-group scratch (static device allocation — allowed).
__device__ float g_loss[G];
__device__ float g_sumb[G];
__device__ float g_sump[G];
__device__ int   g_cntb[G];

// ---------------------------------------------------------------------------
// Block-wide sum over 256 threads (8 warps). All threads get the result.
// ---------------------------------------------------------------------------
__device__ __forceinline__ float blockSum256(float v, float* red)
{
    #pragma unroll
    for (int o = 16; o; o >>= 1) v += __shfl_xor_sync(0xffffffffu, v, o);
    int w = threadIdx.x >> 5;
    if ((threadIdx.x & 31) == 0) red[w] = v;
    __syncthreads();
    float r = (red[0] + red[1]) + (red[2] + red[3])
            + (red[4] + red[5]) + (red[6] + red[7]);
    __syncthreads();
    return r;
}

// ---------------------------------------------------------------------------
// Fused kernel: one CTA (256 threads) per group.
//  Phase A: d[i] = 1 - dot(z_r, z_v) for the group's 128 rows (warp-per-row,
//           2 rows in flight per warp). Writes d to gmem + shared.
//  Phase B: label sums, corr_loss, STABLE counting sort by var_len,
//           neigh_viol, rank_loss (analytic pair count via tie-run end).
// ---------------------------------------------------------------------------
__global__ void __launch_bounds__(256) fused_kernel(
    const float4* __restrict__ zr, const float4* __restrict__ zv,
    const int* __restrict__ var_lens, const int* __restrict__ labels,
    float* __restrict__ dout)
{
    __shared__ float sd[S];      // d (original order)
    __shared__ int   sv[S];      // v (original order)
    __shared__ float sds[S];     // d sorted by v (stable)
    __shared__ int   se[S];      // tie-run end (exclusive) at sorted position
    __shared__ int   cnt[101];   // counting-sort bins
    __shared__ int   P[101];     // exclusive prefix (bin starts); P[100] = S
    __shared__ float red[8];

    const int g    = blockIdx.x;
    const int tid  = threadIdx.x;
    const int w    = tid >> 5;
    const int lane = tid & 31;

    // ---------------- Phase A: row dots ----------------
    {
        const size_t gbase = (size_t)g * S * 32;  // 32 float4 per row
        #pragma unroll 2
        for (int k = 0; k < 8; k++) {
            int r0 = k * 16 + w * 2;
            int r1 = r0 + 1;
            size_t o0 = gbase + (size_t)r0 * 32 + lane;
            size_t o1 = gbase + (size_t)r1 * 32 + lane;
            float4 a0 = zr[o0]; float4 b0 = zv[o0];
            float4 a1 = zr[o1]; float4 b1 = zv[o1];
            float s0 = a0.x*b0.x + a0.y*b0.y + a0.z*b0.z + a0.w*b0.w;
            float s1 = a1.x*b1.x + a1.y*b1.y + a1.z*b1.z + a1.w*b1.w;
            #pragma unroll
            for (int o = 16; o; o >>= 1) {
                s0 += __shfl_xor_sync(0xffffffffu, s0, o);
                s1 += __shfl_xor_sync(0xffffffffu, s1, o);
            }
            if (lane == 0) {
                float d0 = 1.0f - s0, d1 = 1.0f - s1;
                sd[r0] = d0; sd[r1] = d1;
                dout[g * S + r0] = d0;
                dout[g * S + r1] = d1;
            }
        }
    }
    if (tid < 101) cnt[tid] = 0;
    __syncthreads();

    // ---------------- Phase B ----------------
    const bool act = tid < S;
    int   v  = 0, lb = -1;
    float di = 0.0f;
    if (act) {
        int idx = g * S + tid;
        v  = min(max(var_lens[idx], 0), 99);
        lb = labels[idx];
        di = sd[tid];
        sv[tid] = v;
        atomicAdd(&cnt[v], 1);
    }

    // ---- label sums (contrastive term) ----
    float sb = blockSum256(lb == 0 ? di : 0.0f, red);
    float sp = blockSum256(lb == 1 ? di : 0.0f, red);
    float cb = blockSum256(lb == 0 ? 1.0f : 0.0f, red);

    // ---- correlation loss (ddof=1, eps, zero-std guard) ----
    float vf    = act ? (float)v : 0.0f;
    float meanv = blockSum256(vf, red) * (1.0f / S);
    float meand = blockSum256(act ? di : 0.0f, red) * (1.0f / S);
    float dv0 = act ? vf - meanv : 0.0f;
    float dd0 = act ? di - meand : 0.0f;
    float ssv = blockSum256(dv0 * dv0, red);
    float ssd = blockSum256(dd0 * dd0, red);
    float vs = sqrtf(ssv * (1.0f / (S - 1)));
    float ds = sqrtf(ssd * (1.0f / (S - 1)));
    float vz = dv0 / (vs + EPS);
    float dz = dd0 / (ds + EPS);
    float corr = blockSum256(act ? (vz - dz) * (vz - dz) : 0.0f, red) * (1.0f / S);
    if (!(vs > 0.0f && ds > 0.0f)) corr = 0.0f;

    // ---- bin prefix sums (serial over 100 bins) ----
    if (tid == 0) {
        int run = 0;
        #pragma unroll 4
        for (int b = 0; b < 100; b++) { P[b] = run; run += cnt[b]; }
        P[100] = run;   // == S
    }
    __syncthreads();

    // ---- stable scatter: rank among earlier equal keys ----
    if (act) {
        int rank = 0;
        #pragma unroll 8
        for (int j = 0; j < S; j++) rank += (j < tid) & (sv[j] == v);
        int pos = P[v] + rank;
        sds[pos] = di;
        se[pos]  = P[v + 1];   // end (exclusive) of this tie run in sorted order
    }
    __syncthreads();

    // ---- neighbor violation (mean over S-1 adjacent sorted pairs) ----
    float nv = (tid < S - 1) ? fmaxf(sds[tid] - sds[tid + 1] + K_MARGIN, 0.0f) : 0.0f;
    float neigh = blockSum256(nv, red) * (1.0f / (S - 1));

    // ---- rank loss: pairs (i,j) sorted, v[j] > v[i]  <=>  j >= e_i ----
    // Split each row i across 2 threads (h = 0/1) for half the trip count.
    const int   i   = tid & (S - 1);
    const int   h   = tid >> 7;
    const int   e   = se[i];
    const float ddi = sds[i] + K_MARGIN;   // relu(K - (ds[j]-ds[i])) = relu(ddi - ds[j])
    float viol = 0.0f;
    for (int j = e + h; j < S; j += 2)
        viol += fmaxf(ddi - sds[j], 0.0f);
    float ctot = blockSum256(h == 0 ? (float)(S - e) : 0.0f, red);
    float vtot = blockSum256(viol, red);
    float rankl = (ctot > 0.0f) ? vtot / ctot : 0.0f;

    if (tid == 0) {
        g_loss[g] = corr + neigh + rankl;
        g_sumb[g] = sb;
        g_sump[g] = sp;
        g_cntb[g] = (int)cb;
    }
}

// ---------------------------------------------------------------------------
// Finalize: deterministic double-precision reduction -> out[0], out[1].
// ---------------------------------------------------------------------------
__global__ void __launch_bounds__(256) finalize_kernel(float* __restrict__ out)
{
    __shared__ double shL[256], shB[256], shP[256];
    __shared__ long long shC[256];
    int tid = threadIdx.x;

    double aL = 0.0, aB = 0.0, aP = 0.0;
    long long cB = 0;
    for (int g = tid; g < G; g += 256) {
        aL += (double)g_loss[g];
        aB += (double)g_sumb[g];
        aP += (double)g_sump[g];
        cB += (long long)g_cntb[g];
    }
    shL[tid] = aL; shB[tid] = aB; shP[tid] = aP; shC[tid] = cB;
    __syncthreads();
    for (int s = 128; s > 0; s >>= 1) {
        if (tid < s) {
            shL[tid] += shL[tid + s];
            shB[tid] += shB[tid + s];
            shP[tid] += shP[tid + s];
            shC[tid] += shC[tid + s];
        }
        __syncthreads();
    }
    if (tid == 0) {
        long long nb = shC[0];
        long long np = (long long)NTOT - nb;
        double mb = shB[0] / (double)(nb > 1 ? nb : 1);
        double mp = shP[0] / (double)(np > 1 ? np : 1);
        double lcdd = (nb > 0 && np > 0) ? (MARGIN + mb - mp) : 0.0;
        if (lcdd < 0.0) lcdd = 0.0;
        out[0] = (float)lcdd;
        out[1] = (float)(shL[0] / (double)G);
    }
}

// ---------------------------------------------------------------------------
extern "C" void kernel_launch(void* const* d_in, const int* in_sizes, int n_in,
                              void* d_out, int out_size)
{
    const float* zr       = (const float*)d_in[0];
    const float* zv       = (const float*)d_in[1];
    const int*   labels   = (const int*)d_in[2];
    // d_in[3] = groups (== i / S by construction, unused)
    const int*   var_lens = (const int*)d_in[4];
    float* out  = (float*)d_out;
    float* dvec = out + 2;   // d occupies out[2 .. 2+N)

    fused_kernel<<<G, 256>>>((const float4*)zr, (const float4*)zv,
                             var_lens, labels, dvec);
    finalize_kernel<<<1, 256>>>(out);
}

// round 6
// speedup vs baseline: 1.0269x; 1.0116x over previous
#include <cuda_runtime.h>
#include <cuda_bf16.h>

#define NTOT 524288
#define DIM  128
#define S    128
#define G    (NTOT / S)
#define MARGIN   2.0f
#define K_MARGIN 0.02f
#define EPS      1e-6f

// Per-group scratch + completion counter (static device allocation — allowed).
__device__ float g_loss[G];
__device__ float g_sumb[G];
__device__ float g_sump[G];
__device__ int   g_cntb[G];
__device__ int   g_done = 0;   // reset by last CTA each launch -> replay-safe

// ---------------------------------------------------------------------------
// Block-wide sum over 256 threads (8 warps). All threads get the result.
// ---------------------------------------------------------------------------
__device__ __forceinline__ float blockSum256(float v, float* red)
{
    #pragma unroll
    for (int o = 16; o; o >>= 1) v += __shfl_xor_sync(0xffffffffu, v, o);
    int w = threadIdx.x >> 5;
    if ((threadIdx.x & 31) == 0) red[w] = v;
    __syncthreads();
    float r = (red[0] + red[1]) + (red[2] + red[3])
            + (red[4] + red[5]) + (red[6] + red[7]);
    __syncthreads();
    return r;
}

// ---------------------------------------------------------------------------
// Fused kernel: one CTA (256 threads) per group.
//  Phase A: d = 1 - dot(z_r, z_v), warp handles 4 rows/iter (high MLP).
//           d stored to gmem via float2 (dout = out+2 is only 8B-aligned!).
//  Phase B: label sums, corr_loss, stable counting sort, neigh_viol, rank_loss.
//  Phase C: last CTA reduces all per-group partials -> out[0], out[1].
// ---------------------------------------------------------------------------
__global__ void __launch_bounds__(256) fused_kernel(
    const float4* __restrict__ zr, const float4* __restrict__ zv,
    const int* __restrict__ var_lens, const int* __restrict__ labels,
    float* __restrict__ out)
{
    __shared__ float sd[S];      // d (original order)
    __shared__ int   sv[S];      // v (original order)
    __shared__ float sds[S];     // d sorted by v (stable)
    __shared__ int   se[S];      // tie-run end (exclusive) at sorted position
    __shared__ int   cnt[101];   // counting-sort bins
    __shared__ int   P[101];     // exclusive bin prefix; P[100] = S
    __shared__ float red[8];
    __shared__ int   isLast;

    const int g    = blockIdx.x;
    const int tid  = threadIdx.x;
    const int w    = tid >> 5;
    const int lane = tid & 31;
    float* dout = out + 2;       // 8-byte aligned only!

    // ---------------- Phase A: row dots (4 rows per warp per iter) ----------
    {
        const size_t gbase = (size_t)g * S * 32;  // 32 float4 per row
        #pragma unroll
        for (int k = 0; k < 4; k++) {
            int r = k * 32 + w * 4;               // 4 consecutive rows
            size_t o0 = gbase + (size_t)r * 32 + lane;
            float4 a0 = zr[o0],      b0 = zv[o0];
            float4 a1 = zr[o0 + 32], b1 = zv[o0 + 32];
            float4 a2 = zr[o0 + 64], b2 = zv[o0 + 64];
            float4 a3 = zr[o0 + 96], b3 = zv[o0 + 96];
            float s0 = a0.x*b0.x + a0.y*b0.y + a0.z*b0.z + a0.w*b0.w;
            float s1 = a1.x*b1.x + a1.y*b1.y + a1.z*b1.z + a1.w*b1.w;
            float s2 = a2.x*b2.x + a2.y*b2.y + a2.z*b2.z + a2.w*b2.w;
            float s3 = a3.x*b3.x + a3.y*b3.y + a3.z*b3.z + a3.w*b3.w;
            #pragma unroll
            for (int o = 16; o; o >>= 1) {
                s0 += __shfl_xor_sync(0xffffffffu, s0, o);
                s1 += __shfl_xor_sync(0xffffffffu, s1, o);
                s2 += __shfl_xor_sync(0xffffffffu, s2, o);
                s3 += __shfl_xor_sync(0xffffffffu, s3, o);
            }
            if (lane == 0) {
                float d0 = 1.0f - s0, d1 = 1.0f - s1;
                float d2 = 1.0f - s2, d3 = 1.0f - s3;
                sd[r] = d0; sd[r+1] = d1; sd[r+2] = d2; sd[r+3] = d3;
                float* p = dout + g * S + r;       // byte offset 8 + 16k -> 8B aligned
                *(float2*)(p)     = make_float2(d0, d1);
                *(float2*)(p + 2) = make_float2(d2, d3);
            }
        }
    }
    if (tid < 101) cnt[tid] = 0;
    __syncthreads();

    // ---------------- Phase B ----------------
    const bool act = tid < S;
    int   v  = 0, lb = -1;
    float di = 0.0f;
    if (act) {
        int idx = g * S + tid;
        v  = min(max(var_lens[idx], 0), 99);
        lb = labels[idx];
        di = sd[tid];
        sv[tid] = v;
        atomicAdd(&cnt[v], 1);
    }

    // ---- label sums (contrastive term) ----
    float sb = blockSum256(lb == 0 ? di : 0.0f, red);
    float sp = blockSum256(lb == 1 ? di : 0.0f, red);
    float cb = blockSum256(lb == 0 ? 1.0f : 0.0f, red);

    // ---- correlation loss (ddof=1, eps, zero-std guard) ----
    float vf    = act ? (float)v : 0.0f;
    float meanv = blockSum256(vf, red) * (1.0f / S);
    float meand = blockSum256(act ? di : 0.0f, red) * (1.0f / S);
    float dv0 = act ? vf - meanv : 0.0f;
    float dd0 = act ? di - meand : 0.0f;
    float ssv = blockSum256(dv0 * dv0, red);
    float ssd = blockSum256(dd0 * dd0, red);
    float vs = sqrtf(ssv * (1.0f / (S - 1)));
    float ds = sqrtf(ssd * (1.0f / (S - 1)));
    float vz = dv0 / (vs + EPS);
    float dz = dd0 / (ds + EPS);
    float corr = blockSum256(act ? (vz - dz) * (vz - dz) : 0.0f, red) * (1.0f / S);
    if (!(vs > 0.0f && ds > 0.0f)) corr = 0.0f;

    // ---- bin prefix sums (serial over 100 bins) ----
    if (tid == 0) {
        int run = 0;
        #pragma unroll 4
        for (int b = 0; b < 100; b++) { P[b] = run; run += cnt[b]; }
        P[100] = run;   // == S
    }
    __syncthreads();

    // ---- stable scatter: rank among earlier equal keys ----
    if (act) {
        int rank = 0;
        #pragma unroll 8
        for (int j = 0; j < S; j++) rank += (j < tid) & (sv[j] == v);
        int pos = P[v] + rank;
        sds[pos] = di;
        se[pos]  = P[v + 1];   // end (exclusive) of this tie run in sorted order
    }
    __syncthreads();

    // ---- neighbor violation (mean over S-1 adjacent sorted pairs) ----
    float nv = (tid < S - 1) ? fmaxf(sds[tid] - sds[tid + 1] + K_MARGIN, 0.0f) : 0.0f;
    float neigh = blockSum256(nv, red) * (1.0f / (S - 1));

    // ---- rank loss: sorted pairs with v[j] > v[i]  <=>  j >= e_i ----
    const int   i   = tid & (S - 1);
    const int   h   = tid >> 7;
    const int   e   = se[i];
    const float ddi = sds[i] + K_MARGIN;
    float viol = 0.0f;
    for (int j = e + h; j < S; j += 2)
        viol += fmaxf(ddi - sds[j], 0.0f);
    float ctot = blockSum256(h == 0 ? (float)(S - e) : 0.0f, red);
    float vtot = blockSum256(viol, red);
    float rankl = (ctot > 0.0f) ? vtot / ctot : 0.0f;

    if (tid == 0) {
        g_loss[g] = corr + neigh + rankl;
        g_sumb[g] = sb;
        g_sump[g] = sp;
        g_cntb[g] = (int)cb;
        __threadfence();
        int old = atomicAdd(&g_done, 1);
        isLast = (old == G - 1);
    }
    __syncthreads();

    // ---------------- Phase C: last CTA finalizes ----------------
    if (isLast) {
        __shared__ double shL[256], shB[256], shP[256];
        __shared__ long long shC[256];

        double aL = 0.0, aB = 0.0, aP = 0.0;
        long long cB = 0;
        #pragma unroll 4
        for (int q = tid; q < G; q += 256) {
            aL += (double)g_loss[q];
            aB += (double)g_sumb[q];
            aP += (double)g_sump[q];
            cB += (long long)g_cntb[q];
        }
        shL[tid] = aL; shB[tid] = aB; shP[tid] = aP; shC[tid] = cB;
        __syncthreads();
        #pragma unroll
        for (int s = 128; s > 0; s >>= 1) {
            if (tid < s) {
                shL[tid] += shL[tid + s];
                shB[tid] += shB[tid + s];
                shP[tid] += shP[tid + s];
                shC[tid] += shC[tid + s];
            }
            __syncthreads();
        }
        if (tid == 0) {
            long long nb = shC[0];
            long long np = (long long)NTOT - nb;
            double mb = shB[0] / (double)(nb > 1 ? nb : 1);
            double mp = shP[0] / (double)(np > 1 ? np : 1);
            double lcdd = (nb > 0 && np > 0) ? (MARGIN + mb - mp) : 0.0;
            if (lcdd < 0.0) lcdd = 0.0;
            out[0] = (float)lcdd;
            out[1] = (float)(shL[0] / (double)G);
            g_done = 0;            // reset for next graph replay
        }
    }
}

// ---------------------------------------------------------------------------
extern "C" void kernel_launch(void* const* d_in, const int* in_sizes, int n_in,
                              void* d_out, int out_size)
{
    const float* zr       = (const float*)d_in[0];
    const float* zv       = (const float*)d_in[1];
    const int*   labels   = (const int*)d_in[2];
    // d_in[3] = groups (== i / S by construction, unused)
    const int*   var_lens = (const int*)d_in[4];
    float* out = (float*)d_out;

    fused_kernel<<<G, 256>>>((const float4*)zr, (const float4*)zv,
                             var_lens, labels, out);
}

// round 7
// speedup vs baseline: 1.0528x; 1.0252x over previous
#include <cuda_runtime.h>
#include <cuda_bf16.h>

#define NTOT 524288
#define DIM  128
#define S    128
#define G    (NTOT / S)
#define W    1536            // pipeline lag; > max resident CTAs (148*8=1184)
#define MARGIN   2.0f
#define K_MARGIN 0.02f
#define EPS      1e-6f

// Per-group scratch + sync (static device allocation — allowed).
__device__ float g_loss[G];
__device__ float g_sumb[G];
__device__ float g_sump[G];
__device__ int   g_cntb[G];
__device__ int   g_flag[G];    // 0 at load; consumer resets -> replay-safe
__device__ int   g_done = 0;   // reset by last consumer each launch

// ---------------------------------------------------------------------------
// Batched block-wide sum over 256 threads (8 warps). All threads get results.
// ---------------------------------------------------------------------------
template<int K>
__device__ __forceinline__ void blockSumK(float* v, float (*red)[8])
{
    #pragma unroll
    for (int k = 0; k < K; k++)
        #pragma unroll
        for (int o = 16; o; o >>= 1)
            v[k] += __shfl_xor_sync(0xffffffffu, v[k], o);
    int w = threadIdx.x >> 5;
    if ((threadIdx.x & 31) == 0)
        #pragma unroll
        for (int k = 0; k < K; k++) red[k][w] = v[k];
    __syncthreads();
    #pragma unroll
    for (int k = 0; k < K; k++)
        v[k] = (red[k][0] + red[k][1]) + (red[k][2] + red[k][3])
             + (red[k][4] + red[k][5]) + (red[k][6] + red[k][7]);
    __syncthreads();
}

// ---------------------------------------------------------------------------
// Pipelined kernel, grid = G + W CTAs of 256 threads.
//   CTA b < G      : producer — dot products for group b, publish d + flag.
//   CTA b >= W     : consumer — group-phase for group b-W (spin on flag).
//   Last consumer  : final reduction -> out[0], out[1].
// ---------------------------------------------------------------------------
__global__ void __launch_bounds__(256) pipe_kernel(
    const float4* __restrict__ zr, const float4* __restrict__ zv,
    const int* __restrict__ var_lens, const int* __restrict__ labels,
    float* __restrict__ out)
{
    __shared__ int   sv[S];      // v (original order)
    __shared__ float sds[S];     // d sorted by v (stable)
    __shared__ int   se[S];      // tie-run end (exclusive) at sorted position
    __shared__ int   cnt[101];   // counting-sort bins
    __shared__ int   P[101];     // exclusive bin prefix; P[100] = S
    __shared__ float red[5][8];
    __shared__ int   isLast;

    const int b    = blockIdx.x;
    const int tid  = threadIdx.x;
    const int w    = tid >> 5;
    const int lane = tid & 31;
    float* dout = out + 2;       // 8-byte aligned only!

    // ================= Producer: dot products for group b =================
    if (b < G) {
        const size_t gbase = (size_t)b * S * 32;  // 32 float4 per row
        #pragma unroll
        for (int k = 0; k < 4; k++) {
            int r = k * 32 + w * 4;               // 4 consecutive rows per warp
            size_t o0 = gbase + (size_t)r * 32 + lane;
            float4 a0 = zr[o0],      b0 = zv[o0];
            float4 a1 = zr[o0 + 32], b1 = zv[o0 + 32];
            float4 a2 = zr[o0 + 64], b2 = zv[o0 + 64];
            float4 a3 = zr[o0 + 96], b3 = zv[o0 + 96];
            float s0 = a0.x*b0.x + a0.y*b0.y + a0.z*b0.z + a0.w*b0.w;
            float s1 = a1.x*b1.x + a1.y*b1.y + a1.z*b1.z + a1.w*b1.w;
            float s2 = a2.x*b2.x + a2.y*b2.y + a2.z*b2.z + a2.w*b2.w;
            float s3 = a3.x*b3.x + a3.y*b3.y + a3.z*b3.z + a3.w*b3.w;
            #pragma unroll
            for (int o = 16; o; o >>= 1) {
                s0 += __shfl_xor_sync(0xffffffffu, s0, o);
                s1 += __shfl_xor_sync(0xffffffffu, s1, o);
                s2 += __shfl_xor_sync(0xffffffffu, s2, o);
                s3 += __shfl_xor_sync(0xffffffffu, s3, o);
            }
            if (lane == 0) {
                float* p = dout + b * S + r;      // 8B-aligned (out+2)
                *(float2*)(p)     = make_float2(1.0f - s0, 1.0f - s1);
                *(float2*)(p + 2) = make_float2(1.0f - s2, 1.0f - s3);
            }
        }
        __syncthreads();                // all d stores issued
        if (tid == 0) {
            __threadfence();            // release
            *((volatile int*)&g_flag[b]) = 1;
        }
    }

    // ================= Consumer: group-phase for group b-W ================
    if (b < W) return;
    const int g = b - W;

    if (tid < 101) cnt[tid] = 0;
    if (tid == 0) {
        while (*((volatile int*)&g_flag[g]) == 0) __nanosleep(200);
        __threadfence();                // acquire
    }
    __syncthreads();

    const bool act = tid < S;
    int   v  = 0, lb = -1;
    float di = 0.0f;
    if (act) {
        int idx = g * S + tid;
        di = dout[idx];
        v  = min(max(var_lens[idx], 0), 99);
        lb = labels[idx];
        sv[tid] = v;
        atomicAdd(&cnt[v], 1);
    }
    __syncthreads();
    if (tid == 0) *((volatile int*)&g_flag[g]) = 0;   // reset for next replay

    // ---- pass 1: label sums + means (5 sums, one barrier pair) ----
    float vf = act ? (float)v : 0.0f;
    float p1[5] = { lb == 0 ? di : 0.0f, lb == 1 ? di : 0.0f,
                    lb == 0 ? 1.0f : 0.0f, vf, act ? di : 0.0f };
    blockSumK<5>(p1, red);
    float sb = p1[0], sp = p1[1], cb = p1[2];
    float meanv = p1[3] * (1.0f / S);
    float meand = p1[4] * (1.0f / S);

    // ---- pass 2: variances (ddof=1) ----
    float dv0 = act ? vf - meanv : 0.0f;
    float dd0 = act ? di - meand : 0.0f;
    float p2[2] = { dv0 * dv0, dd0 * dd0 };
    blockSumK<2>(p2, red);
    float vs = sqrtf(p2[0] * (1.0f / (S - 1)));
    float ds = sqrtf(p2[1] * (1.0f / (S - 1)));
    float vz = dv0 / (vs + EPS);
    float dz = dd0 / (ds + EPS);

    // ---- pass 3: corr ----
    float p3[1] = { act ? (vz - dz) * (vz - dz) : 0.0f };
    blockSumK<1>(p3, red);
    float corr = p3[0] * (1.0f / S);
    if (!(vs > 0.0f && ds > 0.0f)) corr = 0.0f;

    // ---- bin prefix sums (serial over 100 bins) ----
    if (tid == 0) {
        int run = 0;
        #pragma unroll 4
        for (int q = 0; q < 100; q++) { P[q] = run; run += cnt[q]; }
        P[100] = run;   // == S
    }
    __syncthreads();

    // ---- stable scatter: rank among earlier equal keys ----
    if (act) {
        int rank = 0;
        #pragma unroll 8
        for (int j = 0; j < S; j++) rank += (j < tid) & (sv[j] == v);
        int pos = P[v] + rank;
        sds[pos] = di;
        se[pos]  = P[v + 1];   // end (exclusive) of this tie run
    }
    __syncthreads();

    // ---- pass 4: neigh_viol + rank_loss (3 sums, one barrier pair) ----
    float nv = (tid < S - 1) ? fmaxf(sds[tid] - sds[tid + 1] + K_MARGIN, 0.0f) : 0.0f;
    const int   i   = tid & (S - 1);
    const int   h   = tid >> 7;
    const int   e   = se[i];
    const float ddi = sds[i] + K_MARGIN;
    float viol = 0.0f;
    for (int j = e + h; j < S; j += 2)
        viol += fmaxf(ddi - sds[j], 0.0f);
    float p4[3] = { nv, h == 0 ? (float)(S - e) : 0.0f, viol };
    blockSumK<3>(p4, red);
    float neigh = p4[0] * (1.0f / (S - 1));
    float rankl = (p4[1] > 0.0f) ? p4[2] / p4[1] : 0.0f;

    if (tid == 0) {
        g_loss[g] = corr + neigh + rankl;
        g_sumb[g] = sb;
        g_sump[g] = sp;
        g_cntb[g] = (int)cb;
        __threadfence();
        int old = atomicAdd(&g_done, 1);
        isLast = (old == G - 1);
    }
    __syncthreads();

    // ================= Last consumer finalizes =================
    if (isLast) {
        __shared__ double shL[256], shB[256], shP[256];
        __shared__ long long shC[256];

        double aL = 0.0, aB = 0.0, aP = 0.0;
        long long cB = 0;
        #pragma unroll 4
        for (int q = tid; q < G; q += 256) {
            aL += (double)g_loss[q];
            aB += (double)g_sumb[q];
            aP += (double)g_sump[q];
            cB += (long long)g_cntb[q];
        }
        shL[tid] = aL; shB[tid] = aB; shP[tid] = aP; shC[tid] = cB;
        __syncthreads();
        #pragma unroll
        for (int s = 128; s > 0; s >>= 1) {
            if (tid < s) {
                shL[tid] += shL[tid + s];
                shB[tid] += shB[tid + s];
                shP[tid] += shP[tid + s];
                shC[tid] += shC[tid + s];
            }
            __syncthreads();
        }
        if (tid == 0) {
            long long nb = shC[0];
            long long np = (long long)NTOT - nb;
            double mb = shB[0] / (double)(nb > 1 ? nb : 1);
            double mp = shP[0] / (double)(np > 1 ? np : 1);
            double lcdd = (nb > 0 && np > 0) ? (MARGIN + mb - mp) : 0.0;
            if (lcdd < 0.0) lcdd = 0.0;
            out[0] = (float)lcdd;
            out[1] = (float)(shL[0] / (double)G);
            g_done = 0;            // reset for next graph replay
        }
    }
}

// ---------------------------------------------------------------------------
extern "C" void kernel_launch(void* const* d_in, const int* in_sizes, int n_in,
                              void* d_out, int out_size)
{
    const float* zr       = (const float*)d_in[0];
    const float* zv       = (const float*)d_in[1];
    const int*   labels   = (const int*)d_in[2];
    // d_in[3] = groups (== i / S by construction, unused)
    const int*   var_lens = (const int*)d_in[4];
    float* out = (float*)d_out;

    pipe_kernel<<<G + W, 256>>>((const float4*)zr, (const float4*)zv,
                                var_lens, labels, out);
}